// round 5
// baseline (speedup 1.0000x reference)
#include <cuda_runtime.h>
#include <cuda_bf16.h>
#include <math_constants.h>

#define NN   16384
#define HH   256
#define SMEM_KNN (131072 + 512)

// ---------------- device scratch ----------------
__device__ float          g_sq[NN];
__device__ __nv_bfloat16  g_xb[NN * HH];
__device__ int            g_cand[NN * 16];
__device__ int            g_nbr[NN * 4];
__device__ int            g_bdeg[NN];
__device__ float          g_binv[NN];
__device__ float          g_xt[NN * HH];
__device__ float          g_ef[NN * HH];
__device__ float          g_h1[NN * HH];

// ---------------- helpers ----------------
__device__ __forceinline__ unsigned sptr(const void* p) {
    return (unsigned)__cvta_generic_to_shared(p);
}
__device__ __forceinline__ void ldsm4(unsigned& r0, unsigned& r1, unsigned& r2, unsigned& r3, unsigned addr) {
    asm volatile("ldmatrix.sync.aligned.m8n8.x4.shared.b16 {%0,%1,%2,%3}, [%4];"
                 : "=r"(r0), "=r"(r1), "=r"(r2), "=r"(r3) : "r"(addr));
}
__device__ __forceinline__ void ldsm2(unsigned& r0, unsigned& r1, unsigned addr) {
    asm volatile("ldmatrix.sync.aligned.m8n8.x2.shared.b16 {%0,%1}, [%2];"
                 : "=r"(r0), "=r"(r1) : "r"(addr));
}
__device__ __forceinline__ void mma16816(float& d0, float& d1, float& d2, float& d3,
                                         unsigned a0, unsigned a1, unsigned a2, unsigned a3,
                                         unsigned b0, unsigned b1) {
    asm volatile("mma.sync.aligned.m16n8k16.row.col.f32.bf16.bf16.f32 "
                 "{%0,%1,%2,%3}, {%4,%5,%6,%7}, {%8,%9}, {%0,%1,%2,%3};"
                 : "+f"(d0), "+f"(d1), "+f"(d2), "+f"(d3)
                 : "r"(a0), "r"(a1), "r"(a2), "r"(a3), "r"(b0), "r"(b1));
}

// ---------------- prep: row norms (exact double -> fp32) + bf16 copy ----------------
__global__ void prep_kernel(const float* __restrict__ x) {
    int row = blockIdx.x * 8 + (threadIdx.x >> 5);
    int l   = threadIdx.x & 31;
    const float4* xr = reinterpret_cast<const float4*>(x + row * HH);
    float4 a = xr[2 * l], b = xr[2 * l + 1];
    double s = (double)a.x*a.x + (double)a.y*a.y + (double)a.z*a.z + (double)a.w*a.w
             + (double)b.x*b.x + (double)b.y*b.y + (double)b.z*b.z + (double)b.w*b.w;
#pragma unroll
    for (int o = 16; o; o >>= 1) s += __shfl_xor_sync(0xffffffffu, s, o);
    if (l == 0) g_sq[row] = (float)s;
    union { __nv_bfloat16 h[8]; uint4 u; } cv;
    cv.h[0] = __float2bfloat16(a.x); cv.h[1] = __float2bfloat16(a.y);
    cv.h[2] = __float2bfloat16(a.z); cv.h[3] = __float2bfloat16(a.w);
    cv.h[4] = __float2bfloat16(b.x); cv.h[5] = __float2bfloat16(b.y);
    cv.h[6] = __float2bfloat16(b.z); cv.h[7] = __float2bfloat16(b.w);
    *reinterpret_cast<uint4*>(g_xb + row * HH + l * 8) = cv.u;
}

__global__ void zero_bdeg_kernel() {
    g_bdeg[blockIdx.x * blockDim.x + threadIdx.x] = 0;
}

// ---------------- fused bf16 gram GEMM + per-row top-8x2 candidates ----------------
__global__ __launch_bounds__(256, 1) void knn_kernel() {
    extern __shared__ char sm[];
    char*  sBc = sm + 65536;
    float* d2s = (float*)sBc;
    float* sqc = (float*)(sm + 131072);

    const int t  = threadIdx.x;
    const int rb = blockIdx.x * 128;

    // resident A tile: 128 rows x 256 bf16, xor-swizzled (16B chunks)
#pragma unroll
    for (int u = 0; u < 16; u++) {
        int idx = t + u * 256;
        int R = idx >> 5, C = idx & 31;
        uint4 v = *reinterpret_cast<const uint4*>(g_xb + (rb + R) * HH + C * 8);
        *reinterpret_cast<uint4*>(sm + R * 512 + ((C ^ (R & 7)) << 4)) = v;
    }

    const int w = t >> 5, l = t & 31;
    const int wm = w >> 2, wn = w & 3;      // 2x4 warp grid, warp tile 64x32

    unsigned aBase[4]; int aSw[4];
#pragma unroll
    for (int mt = 0; mt < 4; mt++) {
        int row = wm * 64 + mt * 16 + (l & 15);
        aBase[mt] = sptr(sm) + row * 512;
        aSw[mt] = row & 7;
    }
    unsigned bBase[4]; int bSw[4];
#pragma unroll
    for (int nt = 0; nt < 4; nt++) {
        int row = wn * 32 + nt * 8 + (l & 7);
        bBase[nt] = sptr(sm) + 65536 + row * 512;
        bSw[nt] = row & 7;
    }
    const int khA = (l >> 4) & 1;
    const int khB = (l >> 3) & 1;

    float tv[8]; int ti[8];
#pragma unroll
    for (int k = 0; k < 8; k++) { tv[k] = CUDART_INF_F; ti[k] = 0; }
    const int srow = t >> 1, hh = t & 1;

    for (int it = 0; it < 128; ++it) {
        __syncthreads();                    // previous scan done; B region free
#pragma unroll
        for (int u = 0; u < 16; u++) {
            int idx = t + u * 256;
            int R = idx >> 5, C = idx & 31;
            uint4 v = *reinterpret_cast<const uint4*>(g_xb + (it * 128 + R) * HH + C * 8);
            *reinterpret_cast<uint4*>(sBc + R * 512 + ((C ^ (R & 7)) << 4)) = v;
        }
        if (t < 128) sqc[t] = g_sq[it * 128 + t];
        __syncthreads();

        float acc[4][4][4];
#pragma unroll
        for (int a = 0; a < 4; a++)
#pragma unroll
            for (int b = 0; b < 4; b++)
#pragma unroll
                for (int c = 0; c < 4; c++) acc[a][b][c] = 0.f;

#pragma unroll 4
        for (int ks = 0; ks < 16; ++ks) {
            unsigned af[4][4], bf[4][2];
#pragma unroll
            for (int mt = 0; mt < 4; mt++) {
                int C = 2 * ks + khA;
                ldsm4(af[mt][0], af[mt][1], af[mt][2], af[mt][3],
                      aBase[mt] + ((C ^ aSw[mt]) << 4));
            }
#pragma unroll
            for (int nt = 0; nt < 4; nt++) {
                int C = 2 * ks + khB;
                ldsm2(bf[nt][0], bf[nt][1], bBase[nt] + ((C ^ bSw[nt]) << 4));
            }
#pragma unroll
            for (int mt = 0; mt < 4; mt++)
#pragma unroll
                for (int nt = 0; nt < 4; nt++)
                    mma16816(acc[mt][nt][0], acc[mt][nt][1], acc[mt][nt][2], acc[mt][nt][3],
                             af[mt][0], af[mt][1], af[mt][2], af[mt][3],
                             bf[nt][0], bf[nt][1]);
        }
        __syncthreads();                    // mma reads of B done -> overlay d2

        // ranking value: sq[col] - 2*G (row term constant per row)
#pragma unroll
        for (int mt = 0; mt < 4; mt++) {
#pragma unroll
            for (int nt = 0; nt < 4; nt++) {
                int c0 = wn * 32 + nt * 8 + ((l & 3) << 1);
                float sc0 = sqc[c0], sc1 = sqc[c0 + 1];
#pragma unroll
                for (int p = 0; p < 2; p++) {
                    int row = wm * 64 + mt * 16 + (l >> 2) + p * 8;
                    float v0 = fmaf(-2.f, acc[mt][nt][2 * p],     sc0);
                    float v1 = fmaf(-2.f, acc[mt][nt][2 * p + 1], sc1);
                    int grow = rb + row, gcol = it * 128 + c0;
                    if (grow == gcol)     v0 = CUDART_INF_F;   // exclude self
                    if (grow == gcol + 1) v1 = CUDART_INF_F;
                    d2s[row * 128 + ((c0 + row) & 127)]     = v0;
                    d2s[row * 128 + ((c0 + 1 + row) & 127)] = v1;
                }
            }
        }
        __syncthreads();

        // per-row scan: 2 threads/row, each 64 cols, running top-8
#pragma unroll 4
        for (int s = 0; s < 64; s++) {
            int col = 2 * s + hh;
            float v = d2s[srow * 128 + ((col + srow) & 127)];
            if (v < tv[7]) {
                tv[7] = v; ti[7] = it * 128 + col;
#pragma unroll
                for (int k = 7; k > 0; k--)
                    if (tv[k] < tv[k - 1]) {
                        float tf = tv[k]; tv[k] = tv[k - 1]; tv[k - 1] = tf;
                        int tt = ti[k]; ti[k] = ti[k - 1]; ti[k - 1] = tt;
                    }
            }
        }
    }

    int grow = rb + srow;
#pragma unroll
    for (int k = 0; k < 8; k++) g_cand[grow * 16 + hh * 8 + k] = ti[k];
}

// ---------------- rescore: replicate reference fp32 arithmetic ----------------
// g via ascending-k fp32 FMA chain (cuBLAS SGEMM order: single accumulator,
// sequential k). d2 = fl(fl(sq_i + sq_j) - fl(2*g)). Ties -> lower index.
__global__ void rescore_kernel(const float* __restrict__ x) {
    int wi = (blockIdx.x * blockDim.x + threadIdx.x) >> 5;
    int l  = threadIdx.x & 31;

    float fsqi = g_sq[wi];
    int   cj = (l < 16) ? g_cand[wi * 16 + l] : wi;

    const float4* xi = reinterpret_cast<const float4*>(x + wi * HH);
    const float4* xj = reinterpret_cast<const float4*>(x + cj * HH);

    float acc = 0.f;
#pragma unroll 8
    for (int k4 = 0; k4 < 64; k4++) {
        float4 a = xi[k4];
        float4 b = xj[k4];
        acc = __fmaf_rn(a.x, b.x, acc);
        acc = __fmaf_rn(a.y, b.y, acc);
        acc = __fmaf_rn(a.z, b.z, acc);
        acc = __fmaf_rn(a.w, b.w, acc);
    }

    float dv; int dj;
    if (l < 16) {
        float t = __fadd_rn(fsqi, g_sq[cj]);   // fl(sq_i + sq_j)
        float u = __fmul_rn(2.0f, acc);        // fl(2*g)
        dv = __fsub_rn(t, u);                  // fl(t - u)
        dj = cj;
    } else {
        dv = CUDART_INF_F; dj = 0x7fffffff;
    }

    // top-4 argmin with (value, index) lexicographic order
#pragma unroll
    for (int k = 0; k < 4; k++) {
        float v = dv; int jj = dj;
#pragma unroll
        for (int o = 16; o; o >>= 1) {
            float v2 = __shfl_xor_sync(0xffffffffu, v, o);
            int   j2 = __shfl_xor_sync(0xffffffffu, jj, o);
            if (v2 < v || (v2 == v && j2 < jj)) { v = v2; jj = j2; }
        }
        if (l == 0) { g_nbr[wi * 4 + k] = jj; atomicAdd(&g_bdeg[jj], 1); }
        if (dj == jj) { dv = CUDART_INF_F; dj = 0x7fffffff; }
    }
}

__global__ void binv_kernel() {
    int i = blockIdx.x * blockDim.x + threadIdx.x;
    int d = g_bdeg[i];
    g_binv[i] = d > 0 ? 1.f / (float)d : 0.f;
}

// ---------------- fp32 GEMM: O = A @ W^T  (A[M,256], W[256,256]) ----------------
__global__ __launch_bounds__(256) void gemm_xwt(const float* __restrict__ A,
                                                const float* __restrict__ W,
                                                float* __restrict__ O) {
    __shared__ float sA[64][17];
    __shared__ float sW[256][17];
    int t = threadIdx.x;
    int rb = blockIdx.x * 64;
    int ty = t >> 5, tx = t & 31;
    float acc[8][8];
#pragma unroll
    for (int i = 0; i < 8; i++)
#pragma unroll
        for (int j = 0; j < 8; j++) acc[i][j] = 0.f;

    for (int k0 = 0; k0 < 256; k0 += 16) {
        __syncthreads();
        {
            int r = t >> 2, kc = (t & 3) * 4;
            float4 v = *reinterpret_cast<const float4*>(A + (rb + r) * 256 + k0 + kc);
            sA[r][kc] = v.x; sA[r][kc + 1] = v.y; sA[r][kc + 2] = v.z; sA[r][kc + 3] = v.w;
        }
#pragma unroll
        for (int q = 0; q < 4; q++) {
            int r = (t >> 2) + 64 * q, kc = (t & 3) * 4;
            float4 v = *reinterpret_cast<const float4*>(W + r * 256 + k0 + kc);
            sW[r][kc] = v.x; sW[r][kc + 1] = v.y; sW[r][kc + 2] = v.z; sW[r][kc + 3] = v.w;
        }
        __syncthreads();
#pragma unroll
        for (int kk = 0; kk < 16; kk++) {
            float a[8], b[8];
#pragma unroll
            for (int i = 0; i < 8; i++) a[i] = sA[ty + 8 * i][kk];
#pragma unroll
            for (int j = 0; j < 8; j++) b[j] = sW[tx + 32 * j][kk];
#pragma unroll
            for (int i = 0; i < 8; i++)
#pragma unroll
                for (int j = 0; j < 8; j++) acc[i][j] = fmaf(a[i], b[j], acc[i][j]);
        }
    }
#pragma unroll
    for (int i = 0; i < 8; i++)
#pragma unroll
        for (int j = 0; j < 8; j++)
            O[(rb + ty + 8 * i) * 256 + tx + 32 * j] = acc[i][j];
}

// ---------------- zero hyperedge accumulator ----------------
__global__ void zero_ef_kernel() {
    int i = blockIdx.x * blockDim.x + threadIdx.x;
    reinterpret_cast<float4*>(g_ef)[i] = make_float4(0.f, 0.f, 0.f, 0.f);
}

// ---------------- scatter: e_raw[j] += xt[i] for j in nbr(i) ----------------
__global__ void scatter_kernel(const float* __restrict__ xt) {
    int i = (blockIdx.x * blockDim.x + threadIdx.x) >> 5;
    int l = threadIdx.x & 31;
    const float4* src = reinterpret_cast<const float4*>(xt + i * HH + l * 8);
    float4 v0 = src[0], v1 = src[1];
#pragma unroll
    for (int k = 0; k < 4; k++) {
        int j = g_nbr[i * 4 + k];
        float* dst = g_ef + j * HH + l * 8;
        atomicAdd(dst + 0, v0.x); atomicAdd(dst + 1, v0.y);
        atomicAdd(dst + 2, v0.z); atomicAdd(dst + 3, v0.w);
        atomicAdd(dst + 4, v1.x); atomicAdd(dst + 5, v1.y);
        atomicAdd(dst + 6, v1.z); atomicAdd(dst + 7, v1.w);
    }
}

// ---------------- gather: out = prelu(0.25*sum(Binv[j]*e_raw[j]) + b [+resid]) ----------------
__global__ void gather_kernel(const float* __restrict__ bias,
                              const float* __restrict__ pa,
                              const float* __restrict__ resid,
                              float* __restrict__ out) {
    int i = (blockIdx.x * blockDim.x + threadIdx.x) >> 5;
    int l = threadIdx.x & 31;
    float a = *pa;
    int base = l * 8;
    float acc[8];
#pragma unroll
    for (int f = 0; f < 8; f++) acc[f] = 0.f;
#pragma unroll
    for (int k = 0; k < 4; k++) {
        int j = g_nbr[i * 4 + k];
        float bi = g_binv[j];
        const float4* e = reinterpret_cast<const float4*>(g_ef + j * HH + base);
        float4 e0 = e[0], e1 = e[1];
        acc[0] = fmaf(bi, e0.x, acc[0]); acc[1] = fmaf(bi, e0.y, acc[1]);
        acc[2] = fmaf(bi, e0.z, acc[2]); acc[3] = fmaf(bi, e0.w, acc[3]);
        acc[4] = fmaf(bi, e1.x, acc[4]); acc[5] = fmaf(bi, e1.y, acc[5]);
        acc[6] = fmaf(bi, e1.z, acc[6]); acc[7] = fmaf(bi, e1.w, acc[7]);
    }
    float r[8];
#pragma unroll
    for (int f = 0; f < 8; f++) {
        float v = __fadd_rn(__fmul_rn(0.25f, acc[f]), bias[base + f]);
        if (resid) v = __fadd_rn(v, resid[i * HH + base + f]);
        r[f] = v >= 0.f ? v : a * v;
    }
    float4* o = reinterpret_cast<float4*>(out + i * HH + base);
    o[0] = make_float4(r[0], r[1], r[2], r[3]);
    o[1] = make_float4(r[4], r[5], r[6], r[7]);
}

// ---------------- launch ----------------
extern "C" void kernel_launch(void* const* d_in, const int* in_sizes, int n_in,
                              void* d_out, int out_size) {
    const float* x  = (const float*)d_in[0];
    const float* W1 = (const float*)d_in[2];
    const float* b1 = (const float*)d_in[3];
    const float* W2 = (const float*)d_in[4];
    const float* b2 = (const float*)d_in[5];
    const float* pa = (const float*)d_in[6];
    float* out = (float*)d_out;

    void *p_xt, *p_h1;
    cudaGetSymbolAddress(&p_xt, g_xt);
    cudaGetSymbolAddress(&p_h1, g_h1);
    float* xt = (float*)p_xt;
    float* h1 = (float*)p_h1;

    cudaFuncSetAttribute(knn_kernel, cudaFuncAttributeMaxDynamicSharedMemorySize, SMEM_KNN);

    prep_kernel<<<NN / 8, 256>>>(x);
    zero_bdeg_kernel<<<NN / 256, 256>>>();
    knn_kernel<<<NN / 128, 256, SMEM_KNN>>>();
    rescore_kernel<<<NN / 8, 256>>>(x);
    binv_kernel<<<NN / 256, 256>>>();

    gemm_xwt<<<NN / 64, 256>>>(x, W1, xt);
    zero_ef_kernel<<<NN * HH / 4 / 256, 256>>>();
    scatter_kernel<<<NN / 8, 256>>>(xt);
    gather_kernel<<<NN / 8, 256>>>(b1, pa, nullptr, h1);

    gemm_xwt<<<NN / 64, 256>>>(h1, W2, xt);
    zero_ef_kernel<<<NN * HH / 4 / 256, 256>>>();
    scatter_kernel<<<NN / 8, 256>>>(xt);
    gather_kernel<<<NN / 8, 256>>>(b2, pa, x, out);
}

// round 8
// speedup vs baseline: 1.0297x; 1.0297x over previous
#include <cuda_runtime.h>
#include <cuda_bf16.h>
#include <math_constants.h>
#include <cstdint>

#define NN   16384
#define HH   256

// ---------------- device scratch ----------------
__device__ float          g_sq[NN];
__device__ __nv_bfloat16  g_xb[NN * HH];
__device__ int            g_cand[NN * 16];
__device__ int            g_nbr[NN * 4];
__device__ int            g_bdeg[NN];
__device__ float          g_binv[NN];
__device__ float          g_xt[NN * HH];
__device__ float          g_ef[NN * HH];
__device__ float          g_h1[NN * HH];

// ---------------- helpers ----------------
__device__ __forceinline__ unsigned sptr(const void* p) {
    return (unsigned)__cvta_generic_to_shared(p);
}
__device__ __forceinline__ void ldsm4(unsigned& r0, unsigned& r1, unsigned& r2, unsigned& r3, unsigned addr) {
    asm volatile("ldmatrix.sync.aligned.m8n8.x4.shared.b16 {%0,%1,%2,%3}, [%4];"
                 : "=r"(r0), "=r"(r1), "=r"(r2), "=r"(r3) : "r"(addr));
}
__device__ __forceinline__ void ldsm2(unsigned& r0, unsigned& r1, unsigned addr) {
    asm volatile("ldmatrix.sync.aligned.m8n8.x2.shared.b16 {%0,%1}, [%2];"
                 : "=r"(r0), "=r"(r1) : "r"(addr));
}
__device__ __forceinline__ void mma16816(float& d0, float& d1, float& d2, float& d3,
                                         unsigned a0, unsigned a1, unsigned a2, unsigned a3,
                                         unsigned b0, unsigned b1) {
    asm volatile("mma.sync.aligned.m16n8k16.row.col.f32.bf16.bf16.f32 "
                 "{%0,%1,%2,%3}, {%4,%5,%6,%7}, {%8,%9}, {%0,%1,%2,%3};"
                 : "+f"(d0), "+f"(d1), "+f"(d2), "+f"(d3)
                 : "r"(a0), "r"(a1), "r"(a2), "r"(a3), "r"(b0), "r"(b1));
}
__device__ __forceinline__ void cp_async16(uint32_t saddr, const void* gaddr) {
    asm volatile("cp.async.cg.shared.global [%0], [%1], 16;"
                 :: "r"(saddr), "l"(gaddr) : "memory");
}
#define CP_COMMIT() asm volatile("cp.async.commit_group;" ::: "memory")
#define CP_WAIT0()  asm volatile("cp.async.wait_group 0;" ::: "memory")
#define CP_WAIT1()  asm volatile("cp.async.wait_group 1;" ::: "memory")

// ---------------- prep: row norms (exact double -> fp32) + bf16 copy ----------------
__global__ void prep_kernel(const float* __restrict__ x) {
    int row = blockIdx.x * 8 + (threadIdx.x >> 5);
    int l   = threadIdx.x & 31;
    const float4* xr = reinterpret_cast<const float4*>(x + row * HH);
    float4 a = xr[2 * l], b = xr[2 * l + 1];
    double s = (double)a.x*a.x + (double)a.y*a.y + (double)a.z*a.z + (double)a.w*a.w
             + (double)b.x*b.x + (double)b.y*b.y + (double)b.z*b.z + (double)b.w*b.w;
#pragma unroll
    for (int o = 16; o; o >>= 1) s += __shfl_xor_sync(0xffffffffu, s, o);
    if (l == 0) g_sq[row] = (float)s;
    union { __nv_bfloat16 h[8]; uint4 u; } cv;
    cv.h[0] = __float2bfloat16(a.x); cv.h[1] = __float2bfloat16(a.y);
    cv.h[2] = __float2bfloat16(a.z); cv.h[3] = __float2bfloat16(a.w);
    cv.h[4] = __float2bfloat16(b.x); cv.h[5] = __float2bfloat16(b.y);
    cv.h[6] = __float2bfloat16(b.z); cv.h[7] = __float2bfloat16(b.w);
    *reinterpret_cast<uint4*>(g_xb + row * HH + l * 8) = cv.u;
}

__global__ void zero_bdeg_kernel() {
    g_bdeg[blockIdx.x * blockDim.x + threadIdx.x] = 0;
}

// ---------------- bf16 gram GEMM (cp.async pipelined) + per-row top-8x2 ----------------
// SMEM: A 64K | B0 64K | B1 64K | sq0 512 | sq1 512. d2 scan overlays the dead B[c].
#define KSM_A    0
#define KSM_B0   65536
#define KSM_B1   131072
#define KSM_SQ0  196608
#define KSM_SQ1  197120
#define SMEM_KNN 197632

__global__ __launch_bounds__(256, 1) void knn_kernel() {
    extern __shared__ char sm[];
    const int t  = threadIdx.x;
    const int rb = blockIdx.x * 128;
    const uint32_t smb = sptr(sm);

    // prologue: A tile (rows rb..) + B tile 0 + sq0 via one cp.async group
#pragma unroll
    for (int u = 0; u < 16; u++) {
        int idx = t + u * 256;
        int R = idx >> 5, C = idx & 31;
        uint32_t dsw = (uint32_t)(R * 512 + (((C & 24) | ((C & 7) ^ (R & 7))) << 4));
        cp_async16(smb + KSM_A  + dsw, g_xb + (size_t)(rb + R) * HH + C * 8);
        cp_async16(smb + KSM_B0 + dsw, g_xb + (size_t)R * HH + C * 8);
    }
    if (t < 128) ((float*)(sm + KSM_SQ0))[t] = g_sq[t];
    CP_COMMIT();
    CP_WAIT0();
    __syncthreads();

    const int w = t >> 5, l = t & 31;
    const int wm = w >> 2, wn = w & 3;      // 2x4 warp grid, warp tile 64x32

    uint32_t aBase[4]; int aSw[4];
#pragma unroll
    for (int mt = 0; mt < 4; mt++) {
        int row = wm * 64 + mt * 16 + (l & 15);
        aBase[mt] = smb + KSM_A + row * 512;
        aSw[mt] = row & 7;
    }
    uint32_t bOff[4]; int bSw[4];
#pragma unroll
    for (int nt = 0; nt < 4; nt++) {
        int row = wn * 32 + nt * 8 + (l & 7);
        bOff[nt] = (uint32_t)(row * 512);
        bSw[nt] = row & 7;
    }
    const int khA = (l >> 4) & 1;
    const int khB = (l >> 3) & 1;

    float tv[8]; int ti[8];
#pragma unroll
    for (int k = 0; k < 8; k++) { tv[k] = CUDART_INF_F; ti[k] = 0; }
    const int srow = t >> 1, hh = t & 1;

    for (int it = 0; it < 128; ++it) {
        const int c = it & 1;
        const uint32_t bofs = c ? KSM_B1 : KSM_B0;

        // prefetch tile it+1 into the other B buffer (dead: scanned last iter)
        if (it < 127) {
            const __nv_bfloat16* gsrc = g_xb + (size_t)(it + 1) * 128 * HH;
            uint32_t sb = smb + (c ? KSM_B0 : KSM_B1);
#pragma unroll
            for (int u = 0; u < 16; u++) {
                int idx = t + u * 256;
                int R = idx >> 5, C = idx & 31;
                uint32_t dsw = (uint32_t)(R * 512 + (((C & 24) | ((C & 7) ^ (R & 7))) << 4));
                cp_async16(sb + dsw, gsrc + R * HH + C * 8);
            }
            if (t < 128)
                ((float*)(sm + (c ? KSM_SQ0 : KSM_SQ1)))[t] = g_sq[(it + 1) * 128 + t];
            CP_COMMIT();
            CP_WAIT1();           // group for tile it complete; prefetch in flight
        } else {
            CP_WAIT0();
        }
        __syncthreads();          // B[c] visible to all warps

        const uint32_t bBase = smb + bofs;
        const float* sqc = (const float*)(sm + (c ? KSM_SQ1 : KSM_SQ0));

        float acc[4][4][4];
#pragma unroll
        for (int a = 0; a < 4; a++)
#pragma unroll
            for (int b = 0; b < 4; b++)
#pragma unroll
                for (int cc = 0; cc < 4; cc++) acc[a][b][cc] = 0.f;

#pragma unroll 4
        for (int ks = 0; ks < 16; ++ks) {
            int cA = 2 * ks + khA;
            int cB = 2 * ks + khB;
            unsigned af[4][4], bf[4][2];
#pragma unroll
            for (int mt = 0; mt < 4; mt++)
                ldsm4(af[mt][0], af[mt][1], af[mt][2], af[mt][3],
                      aBase[mt] + (((cA & 24) | ((cA & 7) ^ aSw[mt])) << 4));
#pragma unroll
            for (int nt = 0; nt < 4; nt++)
                ldsm2(bf[nt][0], bf[nt][1],
                      bBase + bOff[nt] + (((cB & 24) | ((cB & 7) ^ bSw[nt])) << 4));
#pragma unroll
            for (int mt = 0; mt < 4; mt++)
#pragma unroll
                for (int nt = 0; nt < 4; nt++)
                    mma16816(acc[mt][nt][0], acc[mt][nt][1], acc[mt][nt][2], acc[mt][nt][3],
                             af[mt][0], af[mt][1], af[mt][2], af[mt][3],
                             bf[nt][0], bf[nt][1]);
        }
        __syncthreads();          // all ldsm reads of B[c] done -> overlay d2

        float* d2s = (float*)(sm + bofs);
        // ranking value: sq[col] - 2*G (row term constant per row)
#pragma unroll
        for (int mt = 0; mt < 4; mt++) {
#pragma unroll
            for (int nt = 0; nt < 4; nt++) {
                int c0 = wn * 32 + nt * 8 + ((l & 3) << 1);
                float sc0 = sqc[c0], sc1 = sqc[c0 + 1];
#pragma unroll
                for (int p = 0; p < 2; p++) {
                    int row = wm * 64 + mt * 16 + (l >> 2) + p * 8;
                    float v0 = fmaf(-2.f, acc[mt][nt][2 * p],     sc0);
                    float v1 = fmaf(-2.f, acc[mt][nt][2 * p + 1], sc1);
                    int grow = rb + row, gcol = it * 128 + c0;
                    if (grow == gcol)     v0 = CUDART_INF_F;   // exclude self
                    if (grow == gcol + 1) v1 = CUDART_INF_F;
                    d2s[row * 128 + ((c0 + row) & 127)]     = v0;
                    d2s[row * 128 + ((c0 + 1 + row) & 127)] = v1;
                }
            }
        }
        __syncthreads();

        // per-row scan: 2 threads/row, each 64 cols, running top-8
#pragma unroll 4
        for (int s = 0; s < 64; s++) {
            int col = 2 * s + hh;
            float v = d2s[srow * 128 + ((col + srow) & 127)];
            if (v < tv[7]) {
                tv[7] = v; ti[7] = it * 128 + col;
#pragma unroll
                for (int k = 7; k > 0; k--)
                    if (tv[k] < tv[k - 1]) {
                        float tf = tv[k]; tv[k] = tv[k - 1]; tv[k - 1] = tf;
                        int tt = ti[k]; ti[k] = ti[k - 1]; ti[k - 1] = tt;
                    }
            }
        }
        __syncthreads();          // scan done before next prefetch overwrites B[c]
    }

    int grow = rb + srow;
#pragma unroll
    for (int k = 0; k < 8; k++) g_cand[grow * 16 + hh * 8 + k] = ti[k];
}

// ---------------- rescore: replicate reference fp32 arithmetic (DO NOT CHANGE) ----------------
__global__ void rescore_kernel(const float* __restrict__ x) {
    int wi = (blockIdx.x * blockDim.x + threadIdx.x) >> 5;
    int l  = threadIdx.x & 31;

    float fsqi = g_sq[wi];
    int   cj = (l < 16) ? g_cand[wi * 16 + l] : wi;

    const float4* xi = reinterpret_cast<const float4*>(x + wi * HH);
    const float4* xj = reinterpret_cast<const float4*>(x + cj * HH);

    float acc = 0.f;
#pragma unroll 8
    for (int k4 = 0; k4 < 64; k4++) {
        float4 a = xi[k4];
        float4 b = xj[k4];
        acc = __fmaf_rn(a.x, b.x, acc);
        acc = __fmaf_rn(a.y, b.y, acc);
        acc = __fmaf_rn(a.z, b.z, acc);
        acc = __fmaf_rn(a.w, b.w, acc);
    }

    float dv; int dj;
    if (l < 16) {
        float tt = __fadd_rn(fsqi, g_sq[cj]);
        float uu = __fmul_rn(2.0f, acc);
        dv = __fsub_rn(tt, uu);
        dj = cj;
    } else {
        dv = CUDART_INF_F; dj = 0x7fffffff;
    }

#pragma unroll
    for (int k = 0; k < 4; k++) {
        float v = dv; int jj = dj;
#pragma unroll
        for (int o = 16; o; o >>= 1) {
            float v2 = __shfl_xor_sync(0xffffffffu, v, o);
            int   j2 = __shfl_xor_sync(0xffffffffu, jj, o);
            if (v2 < v || (v2 == v && j2 < jj)) { v = v2; jj = j2; }
        }
        if (l == 0) { g_nbr[wi * 4 + k] = jj; atomicAdd(&g_bdeg[jj], 1); }
        if (dj == jj) { dv = CUDART_INF_F; dj = 0x7fffffff; }
    }
}

__global__ void binv_kernel() {
    int i = blockIdx.x * blockDim.x + threadIdx.x;
    int d = g_bdeg[i];
    g_binv[i] = d > 0 ? 1.f / (float)d : 0.f;
}

// ---------------- fp32 GEMM: O = A @ W^T ----------------
__global__ __launch_bounds__(256) void gemm_xwt(const float* __restrict__ A,
                                                const float* __restrict__ W,
                                                float* __restrict__ O) {
    __shared__ float sA[64][17];
    __shared__ float sW[256][17];
    int t = threadIdx.x;
    int rb = blockIdx.x * 64;
    int ty = t >> 5, tx = t & 31;
    float acc[8][8];
#pragma unroll
    for (int i = 0; i < 8; i++)
#pragma unroll
        for (int j = 0; j < 8; j++) acc[i][j] = 0.f;

    for (int k0 = 0; k0 < 256; k0 += 16) {
        __syncthreads();
        {
            int r = t >> 2, kc = (t & 3) * 4;
            float4 v = *reinterpret_cast<const float4*>(A + (rb + r) * 256 + k0 + kc);
            sA[r][kc] = v.x; sA[r][kc + 1] = v.y; sA[r][kc + 2] = v.z; sA[r][kc + 3] = v.w;
        }
#pragma unroll
        for (int q = 0; q < 4; q++) {
            int r = (t >> 2) + 64 * q, kc = (t & 3) * 4;
            float4 v = *reinterpret_cast<const float4*>(W + r * 256 + k0 + kc);
            sW[r][kc] = v.x; sW[r][kc + 1] = v.y; sW[r][kc + 2] = v.z; sW[r][kc + 3] = v.w;
        }
        __syncthreads();
#pragma unroll
        for (int kk = 0; kk < 16; kk++) {
            float a[8], b[8];
#pragma unroll
            for (int i = 0; i < 8; i++) a[i] = sA[ty + 8 * i][kk];
#pragma unroll
            for (int j = 0; j < 8; j++) b[j] = sW[tx + 32 * j][kk];
#pragma unroll
            for (int i = 0; i < 8; i++)
#pragma unroll
                for (int j = 0; j < 8; j++) acc[i][j] = fmaf(a[i], b[j], acc[i][j]);
        }
    }
#pragma unroll
    for (int i = 0; i < 8; i++)
#pragma unroll
        for (int j = 0; j < 8; j++)
            O[(rb + ty + 8 * i) * 256 + tx + 32 * j] = acc[i][j];
}

// ---------------- zero hyperedge accumulator ----------------
__global__ void zero_ef_kernel() {
    int i = blockIdx.x * blockDim.x + threadIdx.x;
    reinterpret_cast<float4*>(g_ef)[i] = make_float4(0.f, 0.f, 0.f, 0.f);
}

// ---------------- scatter ----------------
__global__ void scatter_kernel(const float* __restrict__ xt) {
    int i = (blockIdx.x * blockDim.x + threadIdx.x) >> 5;
    int l = threadIdx.x & 31;
    const float4* src = reinterpret_cast<const float4*>(xt + i * HH + l * 8);
    float4 v0 = src[0], v1 = src[1];
#pragma unroll
    for (int k = 0; k < 4; k++) {
        int j = g_nbr[i * 4 + k];
        float* dst = g_ef + j * HH + l * 8;
        atomicAdd(dst + 0, v0.x); atomicAdd(dst + 1, v0.y);
        atomicAdd(dst + 2, v0.z); atomicAdd(dst + 3, v0.w);
        atomicAdd(dst + 4, v1.x); atomicAdd(dst + 5, v1.y);
        atomicAdd(dst + 6, v1.z); atomicAdd(dst + 7, v1.w);
    }
}

// ---------------- gather ----------------
__global__ void gather_kernel(const float* __restrict__ bias,
                              const float* __restrict__ pa,
                              const float* __restrict__ resid,
                              float* __restrict__ out) {
    int i = (blockIdx.x * blockDim.x + threadIdx.x) >> 5;
    int l = threadIdx.x & 31;
    float a = *pa;
    int base = l * 8;
    float acc[8];
#pragma unroll
    for (int f = 0; f < 8; f++) acc[f] = 0.f;
#pragma unroll
    for (int k = 0; k < 4; k++) {
        int j = g_nbr[i * 4 + k];
        float bi = g_binv[j];
        const float4* e = reinterpret_cast<const float4*>(g_ef + j * HH + base);
        float4 e0 = e[0], e1 = e[1];
        acc[0] = fmaf(bi, e0.x, acc[0]); acc[1] = fmaf(bi, e0.y, acc[1]);
        acc[2] = fmaf(bi, e0.z, acc[2]); acc[3] = fmaf(bi, e0.w, acc[3]);
        acc[4] = fmaf(bi, e1.x, acc[4]); acc[5] = fmaf(bi, e1.y, acc[5]);
        acc[6] = fmaf(bi, e1.z, acc[6]); acc[7] = fmaf(bi, e1.w, acc[7]);
    }
    float r[8];
#pragma unroll
    for (int f = 0; f < 8; f++) {
        float v = __fadd_rn(__fmul_rn(0.25f, acc[f]), bias[base + f]);
        if (resid) v = __fadd_rn(v, resid[i * HH + base + f]);
        r[f] = v >= 0.f ? v : a * v;
    }
    float4* o = reinterpret_cast<float4*>(out + i * HH + base);
    o[0] = make_float4(r[0], r[1], r[2], r[3]);
    o[1] = make_float4(r[4], r[5], r[6], r[7]);
}

// ---------------- launch ----------------
extern "C" void kernel_launch(void* const* d_in, const int* in_sizes, int n_in,
                              void* d_out, int out_size) {
    const float* x  = (const float*)d_in[0];
    const float* W1 = (const float*)d_in[2];
    const float* b1 = (const float*)d_in[3];
    const float* W2 = (const float*)d_in[4];
    const float* b2 = (const float*)d_in[5];
    const float* pa = (const float*)d_in[6];
    float* out = (float*)d_out;

    void *p_xt, *p_h1;
    cudaGetSymbolAddress(&p_xt, g_xt);
    cudaGetSymbolAddress(&p_h1, g_h1);
    float* xt = (float*)p_xt;
    float* h1 = (float*)p_h1;

    cudaFuncSetAttribute(knn_kernel, cudaFuncAttributeMaxDynamicSharedMemorySize, SMEM_KNN);

    prep_kernel<<<NN / 8, 256>>>(x);
    zero_bdeg_kernel<<<NN / 256, 256>>>();
    knn_kernel<<<NN / 128, 256, SMEM_KNN>>>();
    rescore_kernel<<<NN / 8, 256>>>(x);
    binv_kernel<<<NN / 256, 256>>>();

    gemm_xwt<<<NN / 64, 256>>>(x, W1, xt);
    zero_ef_kernel<<<NN * HH / 4 / 256, 256>>>();
    scatter_kernel<<<NN / 8, 256>>>(xt);
    gather_kernel<<<NN / 8, 256>>>(b1, pa, nullptr, h1);

    gemm_xwt<<<NN / 64, 256>>>(h1, W2, xt);
    zero_ef_kernel<<<NN * HH / 4 / 256, 256>>>();
    scatter_kernel<<<NN / 8, 256>>>(xt);
    gather_kernel<<<NN / 8, 256>>>(b2, pa, x, out);
}